// round 13
// baseline (speedup 1.0000x reference)
#include <cuda_runtime.h>

// VolumeSDFRenderer: R=262144 rays, N=128 samples/ray.  FINAL (converged).
// inputs (metadata order): distance [R,128] f32, color [R,128,3] f32, depth [R,128] f32
// output: [R,3] f32
//
// Warp per ray; lane l owns samples 4l..4l+3. Five float4 LDG.128 per lane,
// fully coalesced, streaming hints, 32 regs, 256-thread blocks.
// Converged: identical binary measures 94.98-97.02us across runs (+-1% DVFS
// noise) at 6.95-6.99 TB/s = ~87% of HBM spec on 674 MB compulsory traffic.
// Design-space sweep all measured worse or neutral: thread-per-sample 182.8us
// (issue-bound), persistent 2x-buffer 108.1us (occupancy-starved), 128-thr
// blocks 97.0us (neutral). All compute pipes <= 33%; memory-system floor.
//
// NUMERICS (load-bearing): the reference computes tau_i = fl(cumsum(sd)_i) - sd_i
// in fp32 with the huge terminal sd_127 = density*1e10 INSIDE the cumsum; at
// i=127 this collapses to the single quantization fl(T + B) - B ~= 0 giving the
// terminal sample weight ~= 1. We exclude B from the scan (clean exclusive sum)
// and apply the reference's per-element rounding tau = fl(excl + sd) - sd with
// explicit __fadd_rn/__fsub_rn. Weights use the literal formula
// exp(-tau) * (1 - exp(-sd)); no telescoping.

#define SHARP 20.0f
#define NSAMP 128
#define FARD  1e10f

__device__ __forceinline__ float sample_weight(float excl, float sd)
{
    float csum = __fadd_rn(excl, sd);
    float tau  = __fsub_rn(csum, sd);
    return __expf(-tau) * (1.0f - __expf(-sd));
}

__global__ __launch_bounds__(256, 8)
void volsdf_kernel(const float* __restrict__ distance,
                   const float* __restrict__ color,
                   const float* __restrict__ depth,
                   float* __restrict__ out,
                   int R)
{
    const int warp_id = (blockIdx.x * blockDim.x + threadIdx.x) >> 5;
    const int lane    = threadIdx.x & 31;
    if (warp_id >= R) return;
    const int ray = warp_id;

    // ---- coalesced float4 streaming loads: 5 independent LDG.128 per lane ----
    const float4* dist4 = reinterpret_cast<const float4*>(distance + (size_t)ray * NSAMP);
    const float4* dep4  = reinterpret_cast<const float4*>(depth    + (size_t)ray * NSAMP);
    const float4* col4  = reinterpret_cast<const float4*>(color    + (size_t)ray * NSAMP * 3);

    float4 dv = __ldcs(&dist4[lane]);
    float4 zv = __ldcs(&dep4[lane]);
    float4 c0 = __ldcs(&col4[lane * 3 + 0]);   // r0 g0 b0 r1
    float4 c1 = __ldcs(&col4[lane * 3 + 1]);   // g1 b1 r2 g2
    float4 c2 = __ldcs(&col4[lane * 3 + 2]);   // b2 r3 g3 b3

    // ---- deltas: next lane's first depth closes this lane's chunk ----
    float znext = __shfl_down_sync(0xffffffffu, zv.x, 1);
    float dl0 = zv.y - zv.x;
    float dl1 = zv.z - zv.y;
    float dl2 = zv.w - zv.z;
    float dl3 = (lane == 31) ? FARD : (znext - zv.w);

    // ---- sd = density * delta,  density = S*e/(1+e)^2 ----
    float e, op;
    e = __expf(-SHARP * dv.x); op = 1.0f + e; float sd0 = (SHARP * e / (op * op)) * dl0;
    e = __expf(-SHARP * dv.y); op = 1.0f + e; float sd1 = (SHARP * e / (op * op)) * dl1;
    e = __expf(-SHARP * dv.z); op = 1.0f + e; float sd2 = (SHARP * e / (op * op)) * dl2;
    e = __expf(-SHARP * dv.w); op = 1.0f + e; float sd3 = (SHARP * e / (op * op)) * dl3;

    // ---- exclusive scan, EXCLUDING the huge terminal element ----
    float sdz3 = (lane == 31) ? 0.0f : sd3;
    float q0 = sd0;
    float q1 = q0 + sd1;
    float q2 = q1 + sd2;
    float q3 = q2 + sdz3;            // lane total (terminal excluded)

    float incl = q3;
    #pragma unroll
    for (int off = 1; off < 32; off <<= 1) {
        float v = __shfl_up_sync(0xffffffffu, incl, off);
        if (lane >= off) incl += v;
    }
    float base = incl - q3;          // exclusive prefix entering this lane

    // ---- weights: literal reference formula, per-element rounding ----
    float w0 = sample_weight(base,      sd0);
    float w1 = sample_weight(base + q0, sd1);
    float w2 = sample_weight(base + q1, sd2);
    float w3 = sample_weight(base + q2, sd3);  // lane31: fl(T+B)-B cancellation

    // ---- weighted RGB ----
    float fr = w0 * c0.x + w1 * c0.w + w2 * c1.z + w3 * c2.y;
    float fg = w0 * c0.y + w1 * c1.x + w2 * c1.w + w3 * c2.z;
    float fb = w0 * c0.z + w1 * c1.y + w2 * c2.x + w3 * c2.w;

    // ---- warp reduce ----
    #pragma unroll
    for (int off = 16; off > 0; off >>= 1) {
        fr += __shfl_xor_sync(0xffffffffu, fr, off);
        fg += __shfl_xor_sync(0xffffffffu, fg, off);
        fb += __shfl_xor_sync(0xffffffffu, fb, off);
    }

    // lanes 0..2 write one component each (all lanes hold the full sums)
    if (lane < 3) {
        float v = (lane == 0) ? fr : (lane == 1) ? fg : fb;
        __stcs(&out[(size_t)ray * 3 + lane], fminf(fmaxf(v, 0.0f), 1.0f));
    }
}

extern "C" void kernel_launch(void* const* d_in, const int* in_sizes, int n_in,
                              void* d_out, int out_size)
{
    // color = input with the largest element count (R*N*3); the remaining two
    // follow metadata order: distance first, depth second (mapping confirmed by
    // the R2 error-signature experiment).
    int ci = 0;
    for (int k = 1; k < n_in; k++)
        if (in_sizes[k] > in_sizes[ci]) ci = k;

    int others[2], no = 0;
    for (int k = 0; k < n_in && no < 2; k++)
        if (k != ci) others[no++] = k;

    const float* distance = (const float*)d_in[others[0]];
    const float* color    = (const float*)d_in[ci];
    const float* depth    = (const float*)d_in[others[1]];
    float* out = (float*)d_out;

    const int R = in_sizes[ci] / (NSAMP * 3);   // 262144

    int blocks = (R + 7) / 8;                   // 8 warps (rays) per 256-thread block
    volsdf_kernel<<<blocks, 256>>>(distance, color, depth, out, R);
}

// round 15
// speedup vs baseline: 1.0405x; 1.0405x over previous
#include <cuda_runtime.h>

// VolumeSDFRenderer: R=262144 rays, N=128 samples/ray.
// inputs (metadata order): distance [R,128] f32, color [R,128,3] f32, depth [R,128] f32
// output: [R,3] f32
//
// Warp per ray; lane l owns samples 4l..4l+3. Five float4 LDG.128 per lane,
// fully coalesced, streaming hints, 32 regs. R13: final geometry-sweep cell —
// 512-thread blocks (16 warps/CTA); body identical to the converged optimum
// (94.98-96.99us across runs, DRAM ~88%, 6.98 TB/s = ~87% of HBM spec on
// 674 MB compulsory traffic).
//
// NUMERICS (load-bearing): the reference computes tau_i = fl(cumsum(sd)_i) - sd_i
// in fp32 with the huge terminal sd_127 = density*1e10 INSIDE the cumsum; at
// i=127 this collapses to the single quantization fl(T + B) - B ~= 0 giving the
// terminal sample weight ~= 1. We exclude B from the scan (clean exclusive sum)
// and apply the reference's per-element rounding tau = fl(excl + sd) - sd with
// explicit __fadd_rn/__fsub_rn. Weights use the literal formula
// exp(-tau) * (1 - exp(-sd)); no telescoping.

#define SHARP 20.0f
#define NSAMP 128
#define FARD  1e10f

__device__ __forceinline__ float sample_weight(float excl, float sd)
{
    float csum = __fadd_rn(excl, sd);
    float tau  = __fsub_rn(csum, sd);
    return __expf(-tau) * (1.0f - __expf(-sd));
}

__global__ __launch_bounds__(512, 4)
void volsdf_kernel(const float* __restrict__ distance,
                   const float* __restrict__ color,
                   const float* __restrict__ depth,
                   float* __restrict__ out,
                   int R)
{
    const int warp_id = (blockIdx.x * blockDim.x + threadIdx.x) >> 5;
    const int lane    = threadIdx.x & 31;
    if (warp_id >= R) return;
    const int ray = warp_id;

    // ---- coalesced float4 streaming loads: 5 independent LDG.128 per lane ----
    const float4* dist4 = reinterpret_cast<const float4*>(distance + (size_t)ray * NSAMP);
    const float4* dep4  = reinterpret_cast<const float4*>(depth    + (size_t)ray * NSAMP);
    const float4* col4  = reinterpret_cast<const float4*>(color    + (size_t)ray * NSAMP * 3);

    float4 dv = __ldcs(&dist4[lane]);
    float4 zv = __ldcs(&dep4[lane]);
    float4 c0 = __ldcs(&col4[lane * 3 + 0]);   // r0 g0 b0 r1
    float4 c1 = __ldcs(&col4[lane * 3 + 1]);   // g1 b1 r2 g2
    float4 c2 = __ldcs(&col4[lane * 3 + 2]);   // b2 r3 g3 b3

    // ---- deltas: next lane's first depth closes this lane's chunk ----
    float znext = __shfl_down_sync(0xffffffffu, zv.x, 1);
    float dl0 = zv.y - zv.x;
    float dl1 = zv.z - zv.y;
    float dl2 = zv.w - zv.z;
    float dl3 = (lane == 31) ? FARD : (znext - zv.w);

    // ---- sd = density * delta,  density = S*e/(1+e)^2 ----
    float e, op;
    e = __expf(-SHARP * dv.x); op = 1.0f + e; float sd0 = (SHARP * e / (op * op)) * dl0;
    e = __expf(-SHARP * dv.y); op = 1.0f + e; float sd1 = (SHARP * e / (op * op)) * dl1;
    e = __expf(-SHARP * dv.z); op = 1.0f + e; float sd2 = (SHARP * e / (op * op)) * dl2;
    e = __expf(-SHARP * dv.w); op = 1.0f + e; float sd3 = (SHARP * e / (op * op)) * dl3;

    // ---- exclusive scan, EXCLUDING the huge terminal element ----
    float sdz3 = (lane == 31) ? 0.0f : sd3;
    float q0 = sd0;
    float q1 = q0 + sd1;
    float q2 = q1 + sd2;
    float q3 = q2 + sdz3;            // lane total (terminal excluded)

    float incl = q3;
    #pragma unroll
    for (int off = 1; off < 32; off <<= 1) {
        float v = __shfl_up_sync(0xffffffffu, incl, off);
        if (lane >= off) incl += v;
    }
    float base = incl - q3;          // exclusive prefix entering this lane

    // ---- weights: literal reference formula, per-element rounding ----
    float w0 = sample_weight(base,      sd0);
    float w1 = sample_weight(base + q0, sd1);
    float w2 = sample_weight(base + q1, sd2);
    float w3 = sample_weight(base + q2, sd3);  // lane31: fl(T+B)-B cancellation

    // ---- weighted RGB ----
    float fr = w0 * c0.x + w1 * c0.w + w2 * c1.z + w3 * c2.y;
    float fg = w0 * c0.y + w1 * c1.x + w2 * c1.w + w3 * c2.z;
    float fb = w0 * c0.z + w1 * c1.y + w2 * c2.x + w3 * c2.w;

    // ---- warp reduce ----
    #pragma unroll
    for (int off = 16; off > 0; off >>= 1) {
        fr += __shfl_xor_sync(0xffffffffu, fr, off);
        fg += __shfl_xor_sync(0xffffffffu, fg, off);
        fb += __shfl_xor_sync(0xffffffffu, fb, off);
    }

    // lanes 0..2 write one component each (all lanes hold the full sums)
    if (lane < 3) {
        float v = (lane == 0) ? fr : (lane == 1) ? fg : fb;
        __stcs(&out[(size_t)ray * 3 + lane], fminf(fmaxf(v, 0.0f), 1.0f));
    }
}

extern "C" void kernel_launch(void* const* d_in, const int* in_sizes, int n_in,
                              void* d_out, int out_size)
{
    // color = input with the largest element count (R*N*3); the remaining two
    // follow metadata order: distance first, depth second (mapping confirmed by
    // the R2 error-signature experiment).
    int ci = 0;
    for (int k = 1; k < n_in; k++)
        if (in_sizes[k] > in_sizes[ci]) ci = k;

    int others[2], no = 0;
    for (int k = 0; k < n_in && no < 2; k++)
        if (k != ci) others[no++] = k;

    const float* distance = (const float*)d_in[others[0]];
    const float* color    = (const float*)d_in[ci];
    const float* depth    = (const float*)d_in[others[1]];
    float* out = (float*)d_out;

    const int R = in_sizes[ci] / (NSAMP * 3);   // 262144

    int blocks = (R + 15) / 16;                 // 16 warps (rays) per 512-thread block
    volsdf_kernel<<<blocks, 512>>>(distance, color, depth, out, R);
}